// round 1
// baseline (speedup 1.0000x reference)
#include <cuda_runtime.h>

#define EPS 1e-5f
#define SLOPE 0.2f

constexpr int N1 = 10242, N2 = 40962, N3 = 163842;
constexpr int NT = 256;
constexpr int MAXB = 704;   // >= ceil(N3/NT) = 641

// Scratch (allocation-free): ping-pong feature buffers + stats pipeline
__device__ float g_xA[N3 * 8];
__device__ float g_xB[N3 * 8];
__device__ float g_part[MAXB * 16];
__device__ float g_prm[16];   // [0..7] scale, [8..15] shift

// ---------------------------------------------------------------------------
// Block-level (sum, sum^2) accumulation per channel into shared s_acc[2C]
// ---------------------------------------------------------------------------
template <int C>
__device__ __forceinline__ void block_stats(const float* vals, float* s_acc) {
#pragma unroll
    for (int c = 0; c < C; c++) {
        float v = vals[c];
        float v2 = v * v;
#pragma unroll
        for (int o = 16; o > 0; o >>= 1) {
            v  += __shfl_down_sync(0xffffffffu, v,  o);
            v2 += __shfl_down_sync(0xffffffffu, v2, o);
        }
        if ((threadIdx.x & 31) == 0) {
            atomicAdd(&s_acc[c], v);
            atomicAdd(&s_acc[C + c], v2);
        }
    }
}

// ---------------------------------------------------------------------------
// Kernel 1: x0[v,c] = fc_b[3v+c] + sum_j fc_w[(3v+c),j] * h[j],
//           h[j] = age*aw[j] + ab[j].   Also emits per-block stats partials.
// ---------------------------------------------------------------------------
__global__ void k_fc(const float* __restrict__ age, const float* __restrict__ aw,
                     const float* __restrict__ ab, const float* __restrict__ fcw,
                     const float* __restrict__ fcb, float* __restrict__ out) {
    __shared__ float h[64];
    __shared__ float s_acc[6];
    int tid = threadIdx.x;
    if (tid < 64) h[tid] = age[0] * aw[tid] + ab[tid];
    if (tid < 6) s_acc[tid] = 0.f;
    __syncthreads();

    int v = blockIdx.x * NT + tid;
    float vals[3] = {0.f, 0.f, 0.f};
    if (v < N1) {
#pragma unroll
        for (int c = 0; c < 3; c++) {
            int r = 3 * v + c;
            float acc = fcb[r];
            const float4* wr = reinterpret_cast<const float4*>(fcw + (size_t)r * 64);
#pragma unroll
            for (int j = 0; j < 16; j++) {
                float4 w4 = wr[j];
                acc += w4.x * h[4 * j] + w4.y * h[4 * j + 1] +
                       w4.z * h[4 * j + 2] + w4.w * h[4 * j + 3];
            }
            vals[c] = acc;
            out[r] = acc;
        }
    }
    block_stats<3>(vals, s_acc);
    __syncthreads();
    if (tid < 6) g_part[blockIdx.x * 16 + tid] = s_acc[tid];
}

// ---------------------------------------------------------------------------
// Finalize BN: partials -> per-channel scale/shift (folds gamma/beta).
// ---------------------------------------------------------------------------
template <int C>
__global__ void k_fin(int nb, float n, const float* __restrict__ g,
                      const float* __restrict__ b) {
    __shared__ float s[2 * C];
    int tid = threadIdx.x;
    float loc[2 * C];
#pragma unroll
    for (int i = 0; i < 2 * C; i++) loc[i] = 0.f;
    for (int blk = tid; blk < nb; blk += blockDim.x)
#pragma unroll
        for (int i = 0; i < 2 * C; i++) loc[i] += g_part[blk * 16 + i];
    if (tid < 2 * C) s[tid] = 0.f;
    __syncthreads();
#pragma unroll
    for (int i = 0; i < 2 * C; i++) {
        float v = loc[i];
#pragma unroll
        for (int o = 16; o > 0; o >>= 1) v += __shfl_down_sync(0xffffffffu, v, o);
        if ((tid & 31) == 0) atomicAdd(&s[i], v);
    }
    __syncthreads();
    if (tid < C) {
        float m = s[tid] / n;
        float var = s[C + tid] / n - m * m;
        float sc = g[tid] * rsqrtf(var + EPS);
        g_prm[tid] = sc;
        g_prm[8 + tid] = b[tid] - m * sc;
    }
}

// ---------------------------------------------------------------------------
// y-row on demand for upconv: y[idx,c] = b[3j+c] + sum_k lrelu(bn(x[v,k]))*w[3j+c,k]
// with v = idx/7, j = idx%7.
// ---------------------------------------------------------------------------
__device__ __forceinline__ void yrow(const float* __restrict__ x,
                                     const float* sw, const float* sb,
                                     const float* sp, int idx, float* y) {
    int v = idx / 7;
    int j = idx - 7 * v;
    float xn[3];
#pragma unroll
    for (int k = 0; k < 3; k++) {
        float t = x[3 * v + k] * sp[k] + sp[8 + k];
        xn[k] = t >= 0.f ? t : SLOPE * t;
    }
#pragma unroll
    for (int c = 0; c < 3; c++) {
        int r = 3 * j + c;
        y[c] = sb[r] + xn[0] * sw[3 * r] + xn[1] * sw[3 * r + 1] + xn[2] * sw[3 * r + 2];
    }
}

// ---------------------------------------------------------------------------
// Upconv: out[t] = y[top[t]] for t<R; for e=t-R, the reference does
// y[down].reshape(-1,3,2).mean(-1), whose flat layout pairs INTERLEAVED
// channels of rows down[2e], down[2e+1]:
//   out[e,0] = 0.5*(ya[0]+ya[1]); out[e,1] = 0.5*(ya[2]+yb[0]);
//   out[e,2] = 0.5*(yb[1]+yb[2]).
// ---------------------------------------------------------------------------
__global__ void k_upconv(const float* __restrict__ x, const float* __restrict__ w,
                         const float* __restrict__ b, const int* __restrict__ top,
                         const int* __restrict__ down, int R, int Nout,
                         float* __restrict__ out) {
    __shared__ float sw[63], sb[21], sp[16], s_acc[6];
    int tid = threadIdx.x;
    if (tid < 63) sw[tid] = w[tid];
    if (tid < 21) sb[tid] = b[tid];
    if (tid < 16) sp[tid] = g_prm[tid];
    if (tid < 6) s_acc[tid] = 0.f;
    __syncthreads();

    int t = blockIdx.x * NT + tid;
    float vals[3] = {0.f, 0.f, 0.f};
    if (t < Nout) {
        if (t < R) {
            yrow(x, sw, sb, sp, top[t], vals);
        } else {
            int e = t - R;
            int i0 = down[2 * e], i1 = down[2 * e + 1];
            float ya[3], yb[3];
            yrow(x, sw, sb, sp, i0, ya);
            yrow(x, sw, sb, sp, i1, yb);
            vals[0] = 0.5f * (ya[0] + ya[1]);
            vals[1] = 0.5f * (ya[2] + yb[0]);
            vals[2] = 0.5f * (yb[1] + yb[2]);
        }
        out[3 * t]     = vals[0];
        out[3 * t + 1] = vals[1];
        out[3 * t + 2] = vals[2];
    }
    block_stats<3>(vals, s_acc);
    __syncthreads();
    if (tid < 6) g_part[blockIdx.x * 16 + tid] = s_acc[tid];
}

// ---------------------------------------------------------------------------
// One-ring conv: out[n,o] = b[o] + sum_{j,c} lrelu(bn(x[neigh[7n+j],c])) * w[o,7C-major]
// ---------------------------------------------------------------------------
template <int CIN, int COUT, bool STATS>
__global__ void k_onering(const float* __restrict__ x, const float* __restrict__ w,
                          const float* __restrict__ b, const int* __restrict__ neigh,
                          float* __restrict__ out) {
    constexpr int WTOT = COUT * 7 * CIN;
    __shared__ float sw[WTOT];
    __shared__ float sb[COUT];
    __shared__ float sp[16];
    __shared__ float s_acc[2 * COUT];
    int tid = threadIdx.x;
    for (int i = tid; i < WTOT; i += NT) sw[i] = w[i];
    if (tid < COUT) sb[tid] = b[tid];
    if (tid < 16) sp[tid] = g_prm[tid];
    if (STATS && tid < 2 * COUT) s_acc[tid] = 0.f;
    __syncthreads();

    int n = blockIdx.x * NT + tid;
    float acc[COUT];
#pragma unroll
    for (int o = 0; o < COUT; o++) acc[o] = 0.f;

    if (n < N3) {
#pragma unroll
        for (int o = 0; o < COUT; o++) acc[o] = sb[o];
#pragma unroll
        for (int j = 0; j < 7; j++) {
            int v = neigh[7 * n + j];
            float xn[CIN];
            if (CIN == 8) {
                const float4* p = reinterpret_cast<const float4*>(x) + 2 * (size_t)v;
                float4 a = p[0], c4 = p[1];
                float raw[8] = {a.x, a.y, a.z, a.w, c4.x, c4.y, c4.z, c4.w};
#pragma unroll
                for (int c = 0; c < CIN; c++) {
                    float t = raw[c] * sp[c] + sp[8 + c];
                    xn[c] = t >= 0.f ? t : SLOPE * t;
                }
            } else {
#pragma unroll
                for (int c = 0; c < CIN; c++) {
                    float t = x[(size_t)CIN * v + c] * sp[c] + sp[8 + c];
                    xn[c] = t >= 0.f ? t : SLOPE * t;
                }
            }
#pragma unroll
            for (int o = 0; o < COUT; o++)
#pragma unroll
                for (int c = 0; c < CIN; c++)
                    acc[o] += xn[c] * sw[o * 7 * CIN + j * CIN + c];
        }
#pragma unroll
        for (int o = 0; o < COUT; o++) out[(size_t)COUT * n + o] = acc[o];
    }

    if (STATS) {
        block_stats<COUT>(acc, s_acc);
        __syncthreads();
        if (tid < 2 * COUT) g_part[blockIdx.x * 16 + tid] = s_acc[tid];
    }
}

// ---------------------------------------------------------------------------
// Launch: 11 kernels, one stream, fully graph-capturable.
// ---------------------------------------------------------------------------
extern "C" void kernel_launch(void* const* d_in, const int* in_sizes, int n_in,
                              void* d_out, int out_size) {
    const float* age   = (const float*)d_in[0];
    const float* aw    = (const float*)d_in[1];
    const float* ab    = (const float*)d_in[2];
    const float* fcw   = (const float*)d_in[3];
    const float* fcb   = (const float*)d_in[4];
    const float* bnu0g = (const float*)d_in[5];
    const float* bnu0b = (const float*)d_in[6];
    const float* u0w   = (const float*)d_in[7];
    const float* u0b   = (const float*)d_in[8];
    const float* bnu1g = (const float*)d_in[9];
    const float* bnu1b = (const float*)d_in[10];
    const float* u1w   = (const float*)d_in[11];
    const float* u1b   = (const float*)d_in[12];
    const float* bn0g  = (const float*)d_in[13];
    const float* bn0b  = (const float*)d_in[14];
    const float* c0w   = (const float*)d_in[15];
    const float* c0b   = (const float*)d_in[16];
    const float* bn1g  = (const float*)d_in[17];
    const float* bn1b  = (const float*)d_in[18];
    const float* c1w   = (const float*)d_in[19];
    const float* c1b   = (const float*)d_in[20];
    const float* bn2g  = (const float*)d_in[21];
    const float* bn2b  = (const float*)d_in[22];
    const float* c2w   = (const float*)d_in[23];
    const float* c2b   = (const float*)d_in[24];
    const int* top0    = (const int*)d_in[25];
    const int* down0   = (const int*)d_in[26];
    const int* top1    = (const int*)d_in[27];
    const int* down1   = (const int*)d_in[28];
    const int* neigh   = (const int*)d_in[29];

    float *xA, *xB;
    cudaGetSymbolAddress((void**)&xA, g_xA);
    cudaGetSymbolAddress((void**)&xB, g_xB);

    int nb1 = (N1 + NT - 1) / NT;   // 41
    int nb2 = (N2 + NT - 1) / NT;   // 161
    int nb3 = (N3 + NT - 1) / NT;   // 641

    k_fc<<<nb1, NT>>>(age, aw, ab, fcw, fcb, xA);
    k_fin<3><<<1, 256>>>(nb1, (float)N1, bnu0g, bnu0b);

    k_upconv<<<nb2, NT>>>(xA, u0w, u0b, top0, down0, N1, N2, xB);
    k_fin<3><<<1, 256>>>(nb2, (float)N2, bnu1g, bnu1b);

    k_upconv<<<nb3, NT>>>(xB, u1w, u1b, top1, down1, N2, N3, xA);
    k_fin<3><<<1, 256>>>(nb3, (float)N3, bn0g, bn0b);

    k_onering<3, 8, true><<<nb3, NT>>>(xA, c0w, c0b, neigh, xB);
    k_fin<8><<<1, 256>>>(nb3, (float)N3, bn1g, bn1b);

    k_onering<8, 8, true><<<nb3, NT>>>(xB, c1w, c1b, neigh, xA);
    k_fin<8><<<1, 256>>>(nb3, (float)N3, bn2g, bn2b);

    k_onering<8, 2, false><<<nb3, NT>>>(xA, c2w, c2b, neigh, (float*)d_out);
}